// round 1
// baseline (speedup 1.0000x reference)
#include <cuda_runtime.h>

// ---------------- problem constants ----------------
#define B_   16
#define N_   785
#define C_   768
#define H_   12
#define D_   64
#define L_   784          // local tokens
#define W_   28
#define NB_  (2*W_-1)     // 55
#define NREL (NB_*NB_)    // 3025
#define M_   (B_*N_)      // 12560 rows for token GEMMs
#define NN_  (N_*(size_t)N_)  // 616225

// ---------------- scratch (static device globals; no runtime allocs) ------
__device__ float g_qkv[(size_t)B_ * N_ * 3 * C_];   // [B,N,3C]  ~116 MB
__device__ float g_att[(size_t)B_ * N_ * C_];       // [B,N,C]   ~38 MB
__device__ float g_bias[(size_t)H_ * N_ * N_];      // [H,N,N]   ~30 MB

// ===========================================================================
// Bias precompute: bias[h,i,j]
//   i==0 && j==0 : g2g[h]
//   i==0         : g2l[0,h]
//   j==0         : g2l[1,h]
//   else         : rel_table[((qx-kx+27)*55 + (qy-ky+27))*H + h]
// ===========================================================================
__global__ void bias_kernel(const float* __restrict__ rel_table,
                            const float* __restrict__ g2l,
                            const float* __restrict__ g2g) {
    size_t idx = (size_t)blockIdx.x * blockDim.x + threadIdx.x;
    size_t total = (size_t)H_ * NN_;
    if (idx >= total) return;
    int h = (int)(idx / NN_);
    size_t r = idx % NN_;
    int i = (int)(r / N_);
    int j = (int)(r % N_);
    float v;
    if (i == 0) {
        v = (j == 0) ? g2g[h] : g2l[h];          // g2l[0][h][0]
    } else if (j == 0) {
        v = g2l[H_ + h];                          // g2l[1][h][0]
    } else {
        int li = i - 1, lj = j - 1;
        int qx = li / W_, qy = li % W_;
        int kx = lj / W_, ky = lj % W_;
        int ridx = (qx - kx + W_ - 1) * NB_ + (qy - ky + W_ - 1);
        v = rel_table[ridx * H_ + h];
    }
    g_bias[idx] = v;
}

// ===========================================================================
// Tiled SGEMM:  C[m][n] = sum_k A[m][k] * W[n][k]  (+ bias[n])
// Block tile 128x128, K-step 8, 256 threads, 8x8 micro-tiles. K fixed = 768.
// ===========================================================================
template<bool HAS_BIAS>
__global__ __launch_bounds__(256)
void sgemm_nt(const float* __restrict__ A, const float* __restrict__ Wt,
              const float* __restrict__ bias, float* __restrict__ C,
              int M, int Ncols) {
    const int K = C_;
    __shared__ float sA[8][128];
    __shared__ float sB[8][128];

    int tid = threadIdx.x;
    int ty = tid >> 4;           // 0..15
    int tx = tid & 15;           // 0..15
    int n0 = blockIdx.x * 128;
    int m0 = blockIdx.y * 128;

    int rowL = tid >> 1;         // 0..127
    int kc   = (tid & 1) * 4;    // 0 or 4

    float acc[8][8];
#pragma unroll
    for (int i = 0; i < 8; ++i)
#pragma unroll
        for (int j = 0; j < 8; ++j) acc[i][j] = 0.f;

    for (int k0 = 0; k0 < K; k0 += 8) {
        int gm = m0 + rowL;
        float4 fa = make_float4(0.f, 0.f, 0.f, 0.f);
        if (gm < M)
            fa = *(const float4*)(A + (size_t)gm * K + k0 + kc);
        float4 fb = *(const float4*)(Wt + (size_t)(n0 + rowL) * K + k0 + kc);

        sA[kc + 0][rowL] = fa.x; sA[kc + 1][rowL] = fa.y;
        sA[kc + 2][rowL] = fa.z; sA[kc + 3][rowL] = fa.w;
        sB[kc + 0][rowL] = fb.x; sB[kc + 1][rowL] = fb.y;
        sB[kc + 2][rowL] = fb.z; sB[kc + 3][rowL] = fb.w;
        __syncthreads();

#pragma unroll
        for (int kk = 0; kk < 8; ++kk) {
            float4 a0 = *(const float4*)&sA[kk][ty * 8];
            float4 a1 = *(const float4*)&sA[kk][ty * 8 + 4];
            float4 b0 = *(const float4*)&sB[kk][tx * 8];
            float4 b1 = *(const float4*)&sB[kk][tx * 8 + 4];
            float av[8] = {a0.x, a0.y, a0.z, a0.w, a1.x, a1.y, a1.z, a1.w};
            float bv[8] = {b0.x, b0.y, b0.z, b0.w, b1.x, b1.y, b1.z, b1.w};
#pragma unroll
            for (int i = 0; i < 8; ++i)
#pragma unroll
                for (int j = 0; j < 8; ++j)
                    acc[i][j] = fmaf(av[i], bv[j], acc[i][j]);
        }
        __syncthreads();
    }

    // epilogue
#pragma unroll
    for (int i = 0; i < 8; ++i) {
        int gm = m0 + ty * 8 + i;
        if (gm >= M) continue;
        float* cp = C + (size_t)gm * Ncols + n0 + tx * 8;
        float v[8];
#pragma unroll
        for (int j = 0; j < 8; ++j) {
            v[j] = acc[i][j];
            if (HAS_BIAS) v[j] += bias[n0 + tx * 8 + j];
        }
        *(float4*)(cp + 0) = make_float4(v[0], v[1], v[2], v[3]);
        *(float4*)(cp + 4) = make_float4(v[4], v[5], v[6], v[7]);
    }
}

// ===========================================================================
// Flash attention: one block = (64 query rows, one (b,h)).
// Loops over 13 key chunks of 64.  Online softmax, fp32.
// smem: Q/K/V/S tiles, each 64 x 68 floats (stride 68 keeps float4 alignment).
// Thread layout 16x16, each thread owns a 4x4 micro-tile.
// ===========================================================================
#define FSTRIDE 68
#define FTILE   (64 * FSTRIDE)

__global__ __launch_bounds__(256)
void flash_kernel() {
    extern __shared__ float sm[];
    float* sQ = sm;
    float* sK = sm + FTILE;
    float* sV = sm + 2 * FTILE;
    float* sS = sm + 3 * FTILE;

    int tid = threadIdx.x;
    int ty = tid >> 4;      // 0..15 -> rows 4*ty..4*ty+3
    int tx = tid & 15;      // 0..15 -> cols 4*tx..4*tx+3
    int qt = blockIdx.x;    // 0..12
    int bh = blockIdx.y;
    int b = bh / H_, h = bh % H_;

    const float* base = g_qkv + (size_t)b * N_ * (3 * C_);
    const int qoff = h * D_;
    const int koff = C_ + h * D_;
    const int voff = 2 * C_ + h * D_;

    // load Q tile [64 x 64]
#pragma unroll
    for (int it = 0; it < 4; ++it) {
        int lin = it * 256 + tid;
        int r = lin >> 4, d4 = lin & 15;
        int i = qt * 64 + r;
        float4 v = make_float4(0.f, 0.f, 0.f, 0.f);
        if (i < N_) v = *(const float4*)(base + (size_t)i * (3 * C_) + qoff + d4 * 4);
        *(float4*)(sQ + r * FSTRIDE + d4 * 4) = v;
    }

    float accO[4][4];
    float m[4], l[4];
    int iRow[4];
#pragma unroll
    for (int ii = 0; ii < 4; ++ii) {
        m[ii] = -1e30f; l[ii] = 0.f;
        iRow[ii] = qt * 64 + 4 * ty + ii;
#pragma unroll
        for (int jj = 0; jj < 4; ++jj) accO[ii][jj] = 0.f;
    }
    const float* bh_bias = g_bias + (size_t)h * NN_;

    for (int kt = 0; kt < 13; ++kt) {
        __syncthreads();   // previous PV done reading sK/sV/sS

        // load K and V chunks [64 x 64]
#pragma unroll
        for (int it = 0; it < 4; ++it) {
            int lin = it * 256 + tid;
            int r = lin >> 4, d4 = lin & 15;
            int j = kt * 64 + r;
            float4 kv = make_float4(0.f, 0.f, 0.f, 0.f);
            float4 vv = make_float4(0.f, 0.f, 0.f, 0.f);
            if (j < N_) {
                const float* rowp = base + (size_t)j * (3 * C_);
                kv = *(const float4*)(rowp + koff + d4 * 4);
                vv = *(const float4*)(rowp + voff + d4 * 4);
            }
            *(float4*)(sK + r * FSTRIDE + d4 * 4) = kv;
            *(float4*)(sV + r * FSTRIDE + d4 * 4) = vv;
        }

        // bias regs (global, coalesced-ish; L2-resident table)
        float bb[4][4];
#pragma unroll
        for (int ii = 0; ii < 4; ++ii) {
            int i = iRow[ii];
#pragma unroll
            for (int jj = 0; jj < 4; ++jj) {
                int j = kt * 64 + 4 * tx + jj;
                bb[ii][jj] = (i < N_ && j < N_) ? bh_bias[(size_t)i * N_ + j] : 0.f;
            }
        }
        __syncthreads();

        // S = Q K^T
        float s[4][4];
#pragma unroll
        for (int ii = 0; ii < 4; ++ii)
#pragma unroll
            for (int jj = 0; jj < 4; ++jj) s[ii][jj] = 0.f;

#pragma unroll
        for (int d4 = 0; d4 < 16; ++d4) {
            float4 qf[4], kf[4];
#pragma unroll
            for (int ii = 0; ii < 4; ++ii)
                qf[ii] = *(const float4*)(sQ + (4 * ty + ii) * FSTRIDE + d4 * 4);
#pragma unroll
            for (int jj = 0; jj < 4; ++jj)
                kf[jj] = *(const float4*)(sK + (4 * tx + jj) * FSTRIDE + d4 * 4);
#pragma unroll
            for (int ii = 0; ii < 4; ++ii)
#pragma unroll
                for (int jj = 0; jj < 4; ++jj) {
                    s[ii][jj] = fmaf(qf[ii].x, kf[jj].x, s[ii][jj]);
                    s[ii][jj] = fmaf(qf[ii].y, kf[jj].y, s[ii][jj]);
                    s[ii][jj] = fmaf(qf[ii].z, kf[jj].z, s[ii][jj]);
                    s[ii][jj] = fmaf(qf[ii].w, kf[jj].w, s[ii][jj]);
                }
        }

        // scale + bias + mask
#pragma unroll
        for (int ii = 0; ii < 4; ++ii)
#pragma unroll
            for (int jj = 0; jj < 4; ++jj) {
                int j = kt * 64 + 4 * tx + jj;
                s[ii][jj] = (j < N_) ? fmaf(s[ii][jj], 0.125f, bb[ii][jj]) : -1e30f;
            }

        // online softmax per row (reduce across 16 tx lanes)
#pragma unroll
        for (int ii = 0; ii < 4; ++ii) {
            float mx = fmaxf(fmaxf(s[ii][0], s[ii][1]), fmaxf(s[ii][2], s[ii][3]));
#pragma unroll
            for (int ofs = 1; ofs < 16; ofs <<= 1)
                mx = fmaxf(mx, __shfl_xor_sync(0xffffffffu, mx, ofs));
            float mn = fmaxf(m[ii], mx);
            float alpha = __expf(m[ii] - mn);
            float rs = 0.f;
#pragma unroll
            for (int jj = 0; jj < 4; ++jj) {
                float p = __expf(s[ii][jj] - mn);
                s[ii][jj] = p;
                rs += p;
            }
#pragma unroll
            for (int ofs = 1; ofs < 16; ofs <<= 1)
                rs += __shfl_xor_sync(0xffffffffu, rs, ofs);
            l[ii] = l[ii] * alpha + rs;
            m[ii] = mn;
#pragma unroll
            for (int jj = 0; jj < 4; ++jj) accO[ii][jj] *= alpha;
        }

        // write P tile
#pragma unroll
        for (int ii = 0; ii < 4; ++ii)
            *(float4*)(sS + (4 * ty + ii) * FSTRIDE + 4 * tx) =
                make_float4(s[ii][0], s[ii][1], s[ii][2], s[ii][3]);
        __syncthreads();

        // O += P @ V
#pragma unroll
        for (int c4 = 0; c4 < 16; ++c4) {
            float4 pf[4], vf[4];
#pragma unroll
            for (int ii = 0; ii < 4; ++ii)
                pf[ii] = *(const float4*)(sS + (4 * ty + ii) * FSTRIDE + c4 * 4);
#pragma unroll
            for (int cc = 0; cc < 4; ++cc)
                vf[cc] = *(const float4*)(sV + (4 * c4 + cc) * FSTRIDE + 4 * tx);
#pragma unroll
            for (int ii = 0; ii < 4; ++ii) {
                accO[ii][0] += pf[ii].x * vf[0].x + pf[ii].y * vf[1].x +
                               pf[ii].z * vf[2].x + pf[ii].w * vf[3].x;
                accO[ii][1] += pf[ii].x * vf[0].y + pf[ii].y * vf[1].y +
                               pf[ii].z * vf[2].y + pf[ii].w * vf[3].y;
                accO[ii][2] += pf[ii].x * vf[0].z + pf[ii].y * vf[1].z +
                               pf[ii].z * vf[2].z + pf[ii].w * vf[3].z;
                accO[ii][3] += pf[ii].x * vf[0].w + pf[ii].y * vf[1].w +
                               pf[ii].z * vf[2].w + pf[ii].w * vf[3].w;
            }
        }
    }

    // epilogue: normalize and write [B,N,H,d]-flattened att output
#pragma unroll
    for (int ii = 0; ii < 4; ++ii) {
        int i = iRow[ii];
        if (i >= N_) continue;
        float inv = 1.f / l[ii];
        float4 o = make_float4(accO[ii][0] * inv, accO[ii][1] * inv,
                               accO[ii][2] * inv, accO[ii][3] * inv);
        *(float4*)(g_att + ((size_t)b * N_ + i) * C_ + h * D_ + 4 * tx) = o;
    }
}

// ===========================================================================
// launch
// ===========================================================================
extern "C" void kernel_launch(void* const* d_in, const int* in_sizes, int n_in,
                              void* d_out, int out_size) {
    (void)in_sizes; (void)n_in; (void)out_size;
    const float* x         = (const float*)d_in[0];
    const float* qkv_w     = (const float*)d_in[1];
    const float* proj_w    = (const float*)d_in[2];
    const float* proj_b    = (const float*)d_in[3];
    const float* rel_table = (const float*)d_in[4];
    const float* g2l       = (const float*)d_in[5];
    const float* g2g       = (const float*)d_in[6];
    float* out = (float*)d_out;

    float *qkv_p, *att_p;
    cudaGetSymbolAddress((void**)&qkv_p, g_qkv);
    cudaGetSymbolAddress((void**)&att_p, g_att);

    const int smem_flash = 4 * FTILE * (int)sizeof(float);   // 69632 B
    cudaFuncSetAttribute(flash_kernel,
                         cudaFuncAttributeMaxDynamicSharedMemorySize, smem_flash);

    // 1) QKV GEMM: [12560,768] x [2304,768]^T -> g_qkv
    sgemm_nt<false><<<dim3(3 * C_ / 128, (M_ + 127) / 128), 256>>>(
        x, qkv_w, nullptr, qkv_p, M_, 3 * C_);

    // 2) bias table [H,N,N]
    {
        size_t total = (size_t)H_ * NN_;
        bias_kernel<<<(unsigned)((total + 255) / 256), 256>>>(rel_table, g2l, g2g);
    }

    // 3) attention
    flash_kernel<<<dim3(13, B_ * H_), 256, smem_flash>>>();

    // 4) proj GEMM + bias -> out
    sgemm_nt<true><<<dim3(C_ / 128, (M_ + 127) / 128), 256>>>(
        att_p, proj_w, proj_b, out, M_, C_);
}

// round 5
// speedup vs baseline: 1.4845x; 1.4845x over previous
#include <cuda_runtime.h>
#include <cuda_bf16.h>
#include <cstdint>

// ---------------- problem constants ----------------
#define B_   16
#define N_   785
#define C_   768
#define H_   12
#define D_   64
#define W_   28
#define NB_  (2*W_-1)
#define M_   (B_*N_)          // 12560
#define MPAD 12672            // 99*128
#define NN_  (N_*(size_t)N_)  // 616225
#define K_   768

// ---------------- scratch (static device globals) ----------------
__device__ __align__(256) float g_qkv[(size_t)B_ * N_ * 3 * C_];
__device__ __align__(256) float g_att[(size_t)B_ * N_ * C_];
__device__ __align__(256) float g_bias[(size_t)H_ * NN_];
__device__ __align__(256) __nv_bfloat16 g_xh[(size_t)MPAD * K_];
__device__ __align__(256) __nv_bfloat16 g_xl[(size_t)MPAD * K_];
__device__ __align__(256) __nv_bfloat16 g_ah[(size_t)MPAD * K_];
__device__ __align__(256) __nv_bfloat16 g_al[(size_t)MPAD * K_];
__device__ __align__(256) __nv_bfloat16 g_qwh[(size_t)3 * C_ * K_];
__device__ __align__(256) __nv_bfloat16 g_qwl[(size_t)3 * C_ * K_];
__device__ __align__(256) __nv_bfloat16 g_pwh[(size_t)C_ * K_];
__device__ __align__(256) __nv_bfloat16 g_pwl[(size_t)C_ * K_];

// ================= helpers (baseline PTX only: sm_80-class ops) ===========
#define SMEM_SWIZZLE_128B(o) ((o) ^ (((o) >> 3) & 0x70))

__device__ __forceinline__ uint32_t smem_to_u32(const void* p) {
    uint32_t a;
    asm("{ .reg .u64 t; cvta.to.shared.u64 t, %1; cvt.u32.u64 %0, t; }"
        : "=r"(a) : "l"(p));
    return a;
}
__device__ __forceinline__ void cp_async16(uint32_t dst, const void* src) {
    asm volatile("cp.async.cg.shared.global [%0], [%1], 16;" :: "r"(dst), "l"(src));
}
#define CP_COMMIT() asm volatile("cp.async.commit_group;" ::: "memory")
#define CP_WAIT(n)  asm volatile("cp.async.wait_group %0;" :: "n"(n) : "memory")

__device__ __forceinline__ void ldsm_x4(uint32_t* r, uint32_t addr) {
    asm volatile("ldmatrix.sync.aligned.m8n8.x4.shared.b16 {%0,%1,%2,%3}, [%4];"
                 : "=r"(r[0]), "=r"(r[1]), "=r"(r[2]), "=r"(r[3]) : "r"(addr));
}
__device__ __forceinline__ void mma16816(float* c, const uint32_t* a,
                                         uint32_t b0, uint32_t b1) {
    asm volatile("mma.sync.aligned.m16n8k16.row.col.f32.bf16.bf16.f32 "
                 "{%0,%1,%2,%3}, {%4,%5,%6,%7}, {%8,%9}, {%0,%1,%2,%3};"
                 : "+f"(c[0]), "+f"(c[1]), "+f"(c[2]), "+f"(c[3])
                 : "r"(a[0]), "r"(a[1]), "r"(a[2]), "r"(a[3]), "r"(b0), "r"(b1));
}

// ===========================================================================
// fp32 -> bf16 hi/lo split (pads rows [rows, rowsPad) with zeros)
// ===========================================================================
__global__ void split_kernel(const float* __restrict__ in,
                             __nv_bfloat16* __restrict__ hi,
                             __nv_bfloat16* __restrict__ lo,
                             int rows, int rowsPad) {
    int i = blockIdx.x * blockDim.x + threadIdx.x;          // quad index
    int total = rowsPad * (K_ / 4);
    if (i >= total) return;
    int row = (i * 4) / K_;
    float4 v = make_float4(0.f, 0.f, 0.f, 0.f);
    if (row < rows) v = *(const float4*)(in + (size_t)i * 4);
    float vv[4] = {v.x, v.y, v.z, v.w};
    uint32_t hp[2], lp[2];
#pragma unroll
    for (int q = 0; q < 2; ++q) {
        __nv_bfloat16 h0 = __float2bfloat16(vv[2*q]);
        __nv_bfloat16 h1 = __float2bfloat16(vv[2*q+1]);
        __nv_bfloat16 l0 = __float2bfloat16(vv[2*q]   - __bfloat162float(h0));
        __nv_bfloat16 l1 = __float2bfloat16(vv[2*q+1] - __bfloat162float(h1));
        __nv_bfloat162 hh = __nv_bfloat162(h0, h1);
        __nv_bfloat162 ll = __nv_bfloat162(l0, l1);
        hp[q] = *(uint32_t*)&hh; lp[q] = *(uint32_t*)&ll;
    }
    *(uint2*)(hi + (size_t)i * 4) = make_uint2(hp[0], hp[1]);
    *(uint2*)(lo + (size_t)i * 4) = make_uint2(lp[0], lp[1]);
}

// ===========================================================================
// mma.sync bf16 GEMM: C[m][n] = sum_k A[m][k]*W[n][k] (+bias[n])
// 128x128 block tile, KC=64 double-buffered cp.async, SW128 swizzle,
// hi/lo split: AhWh + AhWl + AlWh into fp32 register accumulators.
// 8 warps in 2x4 grid; each warp 64x32 via m16n8k16.
// ===========================================================================
#define KC 64
#define TILE_B 16384            // 128 rows * 128 B
#define STAGE_B (4 * TILE_B)    // Ah,Al,Wh,Wl
#define GEMM_SMEM (2 * STAGE_B) // 131072

__global__ __launch_bounds__(256)
void gemm_mma(const __nv_bfloat16* __restrict__ Ah, const __nv_bfloat16* __restrict__ Al,
              const __nv_bfloat16* __restrict__ Wh, const __nv_bfloat16* __restrict__ Wl,
              const float* __restrict__ bias, float* __restrict__ Cout,
              int M, int Ncols) {
    extern __shared__ char smem[];
    uint32_t sb = smem_to_u32(smem);
    int tid = threadIdx.x;
    int lane = tid & 31, w = tid >> 5;
    int m0 = blockIdx.y * 128, n0 = blockIdx.x * 128;
    int wm = (w >> 2) * 64;        // warp row base (0 / 64)
    int wn = (w & 3) * 32;         // warp col base (0/32/64/96)

    float acc[4][4][4];
#pragma unroll
    for (int a = 0; a < 4; ++a)
#pragma unroll
        for (int b = 0; b < 4; ++b)
#pragma unroll
            for (int c = 0; c < 4; ++c) acc[a][b][c] = 0.f;

    // ldmatrix address components
    uint32_t aRow = lane & 15,  aCol = (lane >> 4) * 16;
    uint32_t bRow = (lane & 7) + ((lane >> 4) & 1) * 8;
    uint32_t bCol = ((lane >> 3) & 1) * 16;

    auto prefetch = [&](int c) {
        uint32_t tb = sb + (uint32_t)(c & 1) * STAGE_B;
        int k0 = c * KC;
#pragma unroll
        for (int it = 0; it < 16; ++it) {
            int g = it * 256 + tid;
            int mat = g >> 10;
            int idx = g & 1023;
            int row = idx >> 3;
            int c16 = idx & 7;
            const __nv_bfloat16* src;
            if (mat == 0)      src = Ah + (size_t)(m0 + row) * K_ + k0 + c16 * 8;
            else if (mat == 1) src = Al + (size_t)(m0 + row) * K_ + k0 + c16 * 8;
            else if (mat == 2) src = Wh + (size_t)(n0 + row) * K_ + k0 + c16 * 8;
            else               src = Wl + (size_t)(n0 + row) * K_ + k0 + c16 * 8;
            uint32_t off = (uint32_t)(row * 128 + c16 * 16);
            cp_async16(tb + mat * TILE_B + SMEM_SWIZZLE_128B(off), src);
        }
        CP_COMMIT();
    };

    prefetch(0);

    for (int c = 0; c < 12; ++c) {
        if (c + 1 < 12) { prefetch(c + 1); CP_WAIT(1); }
        else            { CP_WAIT(0); }
        __syncthreads();

        uint32_t tb = sb + (uint32_t)(c & 1) * STAGE_B;
#pragma unroll
        for (int k16 = 0; k16 < 4; ++k16) {
            uint32_t ah[4][4], al[4][4], bh[2][4], bl[2][4];
#pragma unroll
            for (int mt = 0; mt < 4; ++mt) {
                uint32_t off = SMEM_SWIZZLE_128B(
                    (uint32_t)((wm + mt * 16 + aRow) * 128 + k16 * 32 + aCol));
                ldsm_x4(ah[mt], tb + 0 * TILE_B + off);
                ldsm_x4(al[mt], tb + 1 * TILE_B + off);
            }
#pragma unroll
            for (int nt2 = 0; nt2 < 2; ++nt2) {
                uint32_t off = SMEM_SWIZZLE_128B(
                    (uint32_t)((wn + nt2 * 16 + bRow) * 128 + k16 * 32 + bCol));
                ldsm_x4(bh[nt2], tb + 2 * TILE_B + off);
                ldsm_x4(bl[nt2], tb + 3 * TILE_B + off);
            }
#pragma unroll
            for (int mt = 0; mt < 4; ++mt)
#pragma unroll
                for (int nt = 0; nt < 4; ++nt) {
                    uint32_t b0h = bh[nt >> 1][(nt & 1) * 2];
                    uint32_t b1h = bh[nt >> 1][(nt & 1) * 2 + 1];
                    uint32_t b0l = bl[nt >> 1][(nt & 1) * 2];
                    uint32_t b1l = bl[nt >> 1][(nt & 1) * 2 + 1];
                    mma16816(acc[mt][nt], ah[mt], b0h, b1h);
                    mma16816(acc[mt][nt], ah[mt], b0l, b1l);
                    mma16816(acc[mt][nt], al[mt], b0h, b1h);
                }
        }
        __syncthreads();   // all warps done with buffer before it is refilled
    }

    // epilogue: c0=C[gid][2t], c1=C[gid][2t+1], c2=C[gid+8][2t], c3=C[gid+8][2t+1]
    int gid = lane >> 2, tig = lane & 3;
#pragma unroll
    for (int mt = 0; mt < 4; ++mt) {
#pragma unroll
        for (int nt = 0; nt < 4; ++nt) {
            int col = n0 + wn + nt * 8 + tig * 2;
            float bx = bias ? bias[col] : 0.f;
            float by = bias ? bias[col + 1] : 0.f;
            int r0 = m0 + wm + mt * 16 + gid;
            if (r0 < M) {
                float2 v = make_float2(acc[mt][nt][0] + bx, acc[mt][nt][1] + by);
                *(float2*)(Cout + (size_t)r0 * Ncols + col) = v;
            }
            int r1 = r0 + 8;
            if (r1 < M) {
                float2 v = make_float2(acc[mt][nt][2] + bx, acc[mt][nt][3] + by);
                *(float2*)(Cout + (size_t)r1 * Ncols + col) = v;
            }
        }
    }
}

// ===========================================================================
// Bias precompute (unchanged)
// ===========================================================================
__global__ void bias_kernel(const float* __restrict__ rel_table,
                            const float* __restrict__ g2l,
                            const float* __restrict__ g2g) {
    size_t idx = (size_t)blockIdx.x * blockDim.x + threadIdx.x;
    size_t total = (size_t)H_ * NN_;
    if (idx >= total) return;
    int h = (int)(idx / NN_);
    size_t r = idx % NN_;
    int i = (int)(r / N_);
    int j = (int)(r % N_);
    float v;
    if (i == 0) {
        v = (j == 0) ? g2g[h] : g2l[h];
    } else if (j == 0) {
        v = g2l[H_ + h];
    } else {
        int li = i - 1, lj = j - 1;
        int qx = li / W_, qy = li % W_;
        int kx = lj / W_, ky = lj % W_;
        int ridx = (qx - kx + W_ - 1) * NB_ + (qy - ky + W_ - 1);
        v = rel_table[ridx * H_ + h];
    }
    g_bias[idx] = v;
}

// ===========================================================================
// Flash attention (unchanged from R1 passing version)
// ===========================================================================
#define FSTRIDE 68
#define FTILE   (64 * FSTRIDE)

__global__ __launch_bounds__(256)
void flash_kernel() {
    extern __shared__ float sm[];
    float* sQ = sm;
    float* sK = sm + FTILE;
    float* sV = sm + 2 * FTILE;
    float* sS = sm + 3 * FTILE;

    int tid = threadIdx.x;
    int ty = tid >> 4;
    int tx = tid & 15;
    int qt = blockIdx.x;
    int bh = blockIdx.y;
    int b = bh / H_, h = bh % H_;

    const float* base = g_qkv + (size_t)b * N_ * (3 * C_);
    const int qoff = h * D_;
    const int koff = C_ + h * D_;
    const int voff = 2 * C_ + h * D_;

#pragma unroll
    for (int it = 0; it < 4; ++it) {
        int lin = it * 256 + tid;
        int r = lin >> 4, d4 = lin & 15;
        int i = qt * 64 + r;
        float4 v = make_float4(0.f, 0.f, 0.f, 0.f);
        if (i < N_) v = *(const float4*)(base + (size_t)i * (3 * C_) + qoff + d4 * 4);
        *(float4*)(sQ + r * FSTRIDE + d4 * 4) = v;
    }

    float accO[4][4];
    float m[4], l[4];
    int iRow[4];
#pragma unroll
    for (int ii = 0; ii < 4; ++ii) {
        m[ii] = -1e30f; l[ii] = 0.f;
        iRow[ii] = qt * 64 + 4 * ty + ii;
#pragma unroll
        for (int jj = 0; jj < 4; ++jj) accO[ii][jj] = 0.f;
    }
    const float* bh_bias = g_bias + (size_t)h * NN_;

    for (int kt = 0; kt < 13; ++kt) {
        __syncthreads();

#pragma unroll
        for (int it = 0; it < 4; ++it) {
            int lin = it * 256 + tid;
            int r = lin >> 4, d4 = lin & 15;
            int j = kt * 64 + r;
            float4 kv = make_float4(0.f, 0.f, 0.f, 0.f);
            float4 vv = make_float4(0.f, 0.f, 0.f, 0.f);
            if (j < N_) {
                const float* rowp = base + (size_t)j * (3 * C_);
                kv = *(const float4*)(rowp + koff + d4 * 4);
                vv = *(const float4*)(rowp + voff + d4 * 4);
            }
            *(float4*)(sK + r * FSTRIDE + d4 * 4) = kv;
            *(float4*)(sV + r * FSTRIDE + d4 * 4) = vv;
        }

        float bb[4][4];
#pragma unroll
        for (int ii = 0; ii < 4; ++ii) {
            int i = iRow[ii];
#pragma unroll
            for (int jj = 0; jj < 4; ++jj) {
                int j = kt * 64 + 4 * tx + jj;
                bb[ii][jj] = (i < N_ && j < N_) ? bh_bias[(size_t)i * N_ + j] : 0.f;
            }
        }
        __syncthreads();

        float s[4][4];
#pragma unroll
        for (int ii = 0; ii < 4; ++ii)
#pragma unroll
            for (int jj = 0; jj < 4; ++jj) s[ii][jj] = 0.f;

#pragma unroll
        for (int d4 = 0; d4 < 16; ++d4) {
            float4 qf[4], kf[4];
#pragma unroll
            for (int ii = 0; ii < 4; ++ii)
                qf[ii] = *(const float4*)(sQ + (4 * ty + ii) * FSTRIDE + d4 * 4);
#pragma unroll
            for (int jj = 0; jj < 4; ++jj)
                kf[jj] = *(const float4*)(sK + (4 * tx + jj) * FSTRIDE + d4 * 4);
#pragma unroll
            for (int ii = 0; ii < 4; ++ii)
#pragma unroll
                for (int jj = 0; jj < 4; ++jj) {
                    s[ii][jj] = fmaf(qf[ii].x, kf[jj].x, s[ii][jj]);
                    s[ii][jj] = fmaf(qf[ii].y, kf[jj].y, s[ii][jj]);
                    s[ii][jj] = fmaf(qf[ii].z, kf[jj].z, s[ii][jj]);
                    s[ii][jj] = fmaf(qf[ii].w, kf[jj].w, s[ii][jj]);
                }
        }

#pragma unroll
        for (int ii = 0; ii < 4; ++ii)
#pragma unroll
            for (int jj = 0; jj < 4; ++jj) {
                int j = kt * 64 + 4 * tx + jj;
                s[ii][jj] = (j < N_) ? fmaf(s[ii][jj], 0.125f, bb[ii][jj]) : -1e30f;
            }

#pragma unroll
        for (int ii = 0; ii < 4; ++ii) {
            float mx = fmaxf(fmaxf(s[ii][0], s[ii][1]), fmaxf(s[ii][2], s[ii][3]));
#pragma unroll
            for (int ofs = 1; ofs < 16; ofs <<= 1)
                mx = fmaxf(mx, __shfl_xor_sync(0xffffffffu, mx, ofs));
            float mn = fmaxf(m[ii], mx);
            float alpha = __expf(m[ii] - mn);
            float rs = 0.f;
#pragma unroll
            for (int jj = 0; jj < 4; ++jj) {
                float p = __expf(s[ii][jj] - mn);
                s[ii][jj] = p;
                rs += p;
            }
#pragma unroll
            for (int ofs = 1; ofs < 16; ofs <<= 1)
                rs += __shfl_xor_sync(0xffffffffu, rs, ofs);
            l[ii] = l[ii] * alpha + rs;
            m[ii] = mn;
#pragma unroll
            for (int jj = 0; jj < 4; ++jj) accO[ii][jj] *= alpha;
        }

#pragma unroll
        for (int ii = 0; ii < 4; ++ii)
            *(float4*)(sS + (4 * ty + ii) * FSTRIDE + 4 * tx) =
                make_float4(s[ii][0], s[ii][1], s[ii][2], s[ii][3]);
        __syncthreads();

#pragma unroll
        for (int c4 = 0; c4 < 16; ++c4) {
            float4 pf[4], vf[4];
#pragma unroll
            for (int ii = 0; ii < 4; ++ii)
                pf[ii] = *(const float4*)(sS + (4 * ty + ii) * FSTRIDE + c4 * 4);
#pragma unroll
            for (int cc = 0; cc < 4; ++cc)
                vf[cc] = *(const float4*)(sV + (4 * c4 + cc) * FSTRIDE + 4 * tx);
#pragma unroll
            for (int ii = 0; ii < 4; ++ii) {
                accO[ii][0] += pf[ii].x * vf[0].x + pf[ii].y * vf[1].x +
                               pf[ii].z * vf[2].x + pf[ii].w * vf[3].x;
                accO[ii][1] += pf[ii].x * vf[0].y + pf[ii].y * vf[1].y +
                               pf[ii].z * vf[2].y + pf[ii].w * vf[3].y;
                accO[ii][2] += pf[ii].x * vf[0].z + pf[ii].y * vf[1].z +
                               pf[ii].z * vf[2].z + pf[ii].w * vf[3].z;
                accO[ii][3] += pf[ii].x * vf[0].w + pf[ii].y * vf[1].w +
                               pf[ii].z * vf[2].w + pf[ii].w * vf[3].w;
            }
        }
    }

#pragma unroll
    for (int ii = 0; ii < 4; ++ii) {
        int i = iRow[ii];
        if (i >= N_) continue;
        float inv = 1.f / l[ii];
        float4 o = make_float4(accO[ii][0] * inv, accO[ii][1] * inv,
                               accO[ii][2] * inv, accO[ii][3] * inv);
        *(float4*)(g_att + ((size_t)b * N_ + i) * C_ + h * D_ + 4 * tx) = o;
    }
}

// ===========================================================================
// launch
// ===========================================================================
extern "C" void kernel_launch(void* const* d_in, const int* in_sizes, int n_in,
                              void* d_out, int out_size) {
    (void)in_sizes; (void)n_in; (void)out_size;
    const float* x         = (const float*)d_in[0];
    const float* qkv_w     = (const float*)d_in[1];
    const float* proj_w    = (const float*)d_in[2];
    const float* proj_b    = (const float*)d_in[3];
    const float* rel_table = (const float*)d_in[4];
    const float* g2l       = (const float*)d_in[5];
    const float* g2g       = (const float*)d_in[6];
    float* out = (float*)d_out;

    float *qkv_p, *att_p;
    __nv_bfloat16 *xh, *xl, *ah, *al, *qwh, *qwl, *pwh, *pwl;
    cudaGetSymbolAddress((void**)&qkv_p, g_qkv);
    cudaGetSymbolAddress((void**)&att_p, g_att);
    cudaGetSymbolAddress((void**)&xh, g_xh);
    cudaGetSymbolAddress((void**)&xl, g_xl);
    cudaGetSymbolAddress((void**)&ah, g_ah);
    cudaGetSymbolAddress((void**)&al, g_al);
    cudaGetSymbolAddress((void**)&qwh, g_qwh);
    cudaGetSymbolAddress((void**)&qwl, g_qwl);
    cudaGetSymbolAddress((void**)&pwh, g_pwh);
    cudaGetSymbolAddress((void**)&pwl, g_pwl);

    const int smem_flash = 4 * FTILE * (int)sizeof(float);
    cudaFuncSetAttribute(flash_kernel,
                         cudaFuncAttributeMaxDynamicSharedMemorySize, smem_flash);
    cudaFuncSetAttribute(gemm_mma,
                         cudaFuncAttributeMaxDynamicSharedMemorySize, GEMM_SMEM);

    // bf16 hi/lo splits
    {
        int tot = MPAD * (K_ / 4);
        split_kernel<<<(tot + 255) / 256, 256>>>(x, xh, xl, M_, MPAD);
    }
    {
        int tot = 3 * C_ * (K_ / 4);
        split_kernel<<<(tot + 255) / 256, 256>>>(qkv_w, qwh, qwl, 3 * C_, 3 * C_);
    }
    {
        int tot = C_ * (K_ / 4);
        split_kernel<<<(tot + 255) / 256, 256>>>(proj_w, pwh, pwl, C_, C_);
    }

    // bias table [H,N,N]
    {
        size_t total = (size_t)H_ * NN_;
        bias_kernel<<<(unsigned)((total + 255) / 256), 256>>>(rel_table, g2l, g2g);
    }

    // 1) QKV GEMM (mma.sync bf16 hi/lo)
    gemm_mma<<<dim3(3 * C_ / 128, MPAD / 128), 256, GEMM_SMEM>>>(
        xh, xl, qwh, qwl, nullptr, qkv_p, M_, 3 * C_);

    // 2) attention
    flash_kernel<<<dim3(13, B_ * H_), 256, smem_flash>>>();

    // 3) att -> bf16 split
    {
        int tot = MPAD * (K_ / 4);
        split_kernel<<<(tot + 255) / 256, 256>>>(att_p, ah, al, M_, MPAD);
    }

    // 4) proj GEMM (mma.sync bf16 hi/lo) + bias
    gemm_mma<<<dim3(C_ / 128, MPAD / 128), 256, GEMM_SMEM>>>(
        ah, al, pwh, pwl, proj_b, out, M_, C_);
}

// round 15
// speedup vs baseline: 3.3290x; 2.2425x over previous
#include <cuda_runtime.h>
#include <cuda_bf16.h>
#include <cstdint>

// ---------------- problem constants ----------------
#define B_   16
#define N_   785
#define C_   768
#define H_   12
#define D_   64
#define W_   28
#define NB_  (2*W_-1)
#define M_   (B_*N_)          // 12560
#define MPAD 12672            // 99*128
#define K_   768
#define NP_  896              // padded token count (7*128)
#define BH_  (B_*H_)          // 192

// ---------------- scratch (static device globals; bss => zero) ------------
__device__ __align__(256) float g_bias[(size_t)H_ * NP_ * NP_];
__device__ __align__(256) __nv_bfloat16 g_xh[(size_t)MPAD * K_];
__device__ __align__(256) __nv_bfloat16 g_xl[(size_t)MPAD * K_];
__device__ __align__(256) __nv_bfloat16 g_qkvh[(size_t)MPAD * 3 * C_];
__device__ __align__(256) __nv_bfloat16 g_qkvl[(size_t)MPAD * 3 * C_];
__device__ __align__(256) __nv_bfloat16 g_vth[(size_t)BH_ * D_ * NP_];
__device__ __align__(256) __nv_bfloat16 g_vtl[(size_t)BH_ * D_ * NP_];
__device__ __align__(256) __nv_bfloat16 g_ah[(size_t)MPAD * K_];
__device__ __align__(256) __nv_bfloat16 g_al[(size_t)MPAD * K_];
__device__ __align__(256) __nv_bfloat16 g_qwh[(size_t)3 * C_ * K_];
__device__ __align__(256) __nv_bfloat16 g_qwl[(size_t)3 * C_ * K_];
__device__ __align__(256) __nv_bfloat16 g_pwh[(size_t)C_ * K_];
__device__ __align__(256) __nv_bfloat16 g_pwl[(size_t)C_ * K_];

// ================= helpers (baseline PTX only) ===========
#define SMEM_SWIZZLE_128B(o) ((o) ^ (((o) >> 3) & 0x70))

__device__ __forceinline__ uint32_t smem_to_u32(const void* p) {
    uint32_t a;
    asm("{ .reg .u64 t; cvta.to.shared.u64 t, %1; cvt.u32.u64 %0, t; }"
        : "=r"(a) : "l"(p));
    return a;
}
__device__ __forceinline__ void cp_async16(uint32_t dst, const void* src) {
    asm volatile("cp.async.cg.shared.global [%0], [%1], 16;" :: "r"(dst), "l"(src));
}
#define CP_COMMIT() asm volatile("cp.async.commit_group;" ::: "memory")
#define CP_WAIT(n)  asm volatile("cp.async.wait_group %0;" :: "n"(n) : "memory")

__device__ __forceinline__ void ldsm_x4(uint32_t* r, uint32_t addr) {
    asm volatile("ldmatrix.sync.aligned.m8n8.x4.shared.b16 {%0,%1,%2,%3}, [%4];"
                 : "=r"(r[0]), "=r"(r[1]), "=r"(r[2]), "=r"(r[3]) : "r"(addr));
}
__device__ __forceinline__ void mma16816(float* c, const uint32_t* a,
                                         uint32_t b0, uint32_t b1) {
    asm volatile("mma.sync.aligned.m16n8k16.row.col.f32.bf16.bf16.f32 "
                 "{%0,%1,%2,%3}, {%4,%5,%6,%7}, {%8,%9}, {%0,%1,%2,%3};"
                 : "+f"(c[0]), "+f"(c[1]), "+f"(c[2]), "+f"(c[3])
                 : "r"(a[0]), "r"(a[1]), "r"(a[2]), "r"(a[3]), "r"(b0), "r"(b1));
}
__device__ __forceinline__ uint32_t pack_bf16(float a, float b) {
    __nv_bfloat162 t(__float2bfloat16(a), __float2bfloat16(b));
    return *(uint32_t*)&t;
}
__device__ __forceinline__ float bf16_val(float v) {
    return __bfloat162float(__float2bfloat16(v));
}

// ===========================================================================
// fp32 -> bf16 hi/lo split (pads rows [rows, rowsPad) with zeros)
// ===========================================================================
__global__ void split_kernel(const float* __restrict__ in,
                             __nv_bfloat16* __restrict__ hi,
                             __nv_bfloat16* __restrict__ lo,
                             int rows, int rowsPad) {
    int i = blockIdx.x * blockDim.x + threadIdx.x;
    int total = rowsPad * (K_ / 4);
    if (i >= total) return;
    int row = (i * 4) / K_;
    float4 v = make_float4(0.f, 0.f, 0.f, 0.f);
    if (row < rows) v = *(const float4*)(in + (size_t)i * 4);
    float vv[4] = {v.x, v.y, v.z, v.w};
    uint32_t hp[2], lp[2];
#pragma unroll
    for (int q = 0; q < 2; ++q) {
        float a = vv[2*q], b = vv[2*q+1];
        float ha = bf16_val(a), hb = bf16_val(b);
        hp[q] = pack_bf16(a, b);
        lp[q] = pack_bf16(a - ha, b - hb);
    }
    *(uint2*)(hi + (size_t)i * 4) = make_uint2(hp[0], hp[1]);
    *(uint2*)(lo + (size_t)i * 4) = make_uint2(lp[0], lp[1]);
}

// ===========================================================================
// mma.sync bf16 GEMM, 128x128 tile, KC=64 double-buffered.
// OUTB=0: fp32 out (+bias). OUTB=1: bf16 hi/lo out (no bias).
// ===========================================================================
#define KC 64
#define TILE_B 16384
#define STAGE_B (4 * TILE_B)
#define GEMM_SMEM (2 * STAGE_B)

template<int OUTB>
__global__ __launch_bounds__(256)
void gemm_mma(const __nv_bfloat16* __restrict__ Ah, const __nv_bfloat16* __restrict__ Al,
              const __nv_bfloat16* __restrict__ Wh, const __nv_bfloat16* __restrict__ Wl,
              const float* __restrict__ bias, float* __restrict__ Cout,
              uint32_t* __restrict__ Chi, uint32_t* __restrict__ Clo,
              int M, int Ncols) {
    extern __shared__ char smem[];
    uint32_t sb = smem_to_u32(smem);
    int tid = threadIdx.x;
    int lane = tid & 31, w = tid >> 5;
    int m0 = blockIdx.y * 128, n0 = blockIdx.x * 128;
    int wm = (w >> 2) * 64;
    int wn = (w & 3) * 32;

    float acc[4][4][4];
#pragma unroll
    for (int a = 0; a < 4; ++a)
#pragma unroll
        for (int b = 0; b < 4; ++b)
#pragma unroll
            for (int c = 0; c < 4; ++c) acc[a][b][c] = 0.f;

    uint32_t aRow = lane & 15,  aCol = (lane >> 4) * 16;
    uint32_t bRow = (lane & 7) + ((lane >> 4) & 1) * 8;
    uint32_t bCol = ((lane >> 3) & 1) * 16;

    auto prefetch = [&](int c) {
        uint32_t tb = sb + (uint32_t)(c & 1) * STAGE_B;
        int k0 = c * KC;
#pragma unroll
        for (int it = 0; it < 16; ++it) {
            int g = it * 256 + tid;
            int mat = g >> 10;
            int idx = g & 1023;
            int row = idx >> 3;
            int c16 = idx & 7;
            const __nv_bfloat16* src;
            if (mat == 0)      src = Ah + (size_t)(m0 + row) * K_ + k0 + c16 * 8;
            else if (mat == 1) src = Al + (size_t)(m0 + row) * K_ + k0 + c16 * 8;
            else if (mat == 2) src = Wh + (size_t)(n0 + row) * K_ + k0 + c16 * 8;
            else               src = Wl + (size_t)(n0 + row) * K_ + k0 + c16 * 8;
            uint32_t off = (uint32_t)(row * 128 + c16 * 16);
            cp_async16(tb + mat * TILE_B + SMEM_SWIZZLE_128B(off), src);
        }
        CP_COMMIT();
    };

    prefetch(0);

    for (int c = 0; c < 12; ++c) {
        if (c + 1 < 12) { prefetch(c + 1); CP_WAIT(1); }
        else            { CP_WAIT(0); }
        __syncthreads();

        uint32_t tb = sb + (uint32_t)(c & 1) * STAGE_B;
#pragma unroll
        for (int k16 = 0; k16 < 4; ++k16) {
            uint32_t ah[4][4], al[4][4], bh[2][4], bl[2][4];
#pragma unroll
            for (int mt = 0; mt < 4; ++mt) {
                uint32_t off = SMEM_SWIZZLE_128B(
                    (uint32_t)((wm + mt * 16 + aRow) * 128 + k16 * 32 + aCol));
                ldsm_x4(ah[mt], tb + 0 * TILE_B + off);
                ldsm_x4(al[mt], tb + 1 * TILE_B + off);
            }
#pragma unroll
            for (int nt2 = 0; nt2 < 2; ++nt2) {
                uint32_t off = SMEM_SWIZZLE_128B(
                    (uint32_t)((wn + nt2 * 16 + bRow) * 128 + k16 * 32 + bCol));
                ldsm_x4(bh[nt2], tb + 2 * TILE_B + off);
                ldsm_x4(bl[nt2], tb + 3 * TILE_B + off);
            }
#pragma unroll
            for (int mt = 0; mt < 4; ++mt)
#pragma unroll
                for (int nt = 0; nt < 4; ++nt) {
                    uint32_t b0h = bh[nt >> 1][(nt & 1) * 2];
                    uint32_t b1h = bh[nt >> 1][(nt & 1) * 2 + 1];
                    uint32_t b0l = bl[nt >> 1][(nt & 1) * 2];
                    uint32_t b1l = bl[nt >> 1][(nt & 1) * 2 + 1];
                    mma16816(acc[mt][nt], ah[mt], b0h, b1h);
                    mma16816(acc[mt][nt], ah[mt], b0l, b1l);
                    mma16816(acc[mt][nt], al[mt], b0h, b1h);
                }
        }
        __syncthreads();
    }

    int gid = lane >> 2, tig = lane & 3;
#pragma unroll
    for (int mt = 0; mt < 4; ++mt) {
#pragma unroll
        for (int nt = 0; nt < 4; ++nt) {
            int col = n0 + wn + nt * 8 + tig * 2;
            int r0 = m0 + wm + mt * 16 + gid;
            int r1 = r0 + 8;
            if (OUTB == 0) {
                float bx = bias ? bias[col] : 0.f;
                float by = bias ? bias[col + 1] : 0.f;
                if (r0 < M) {
                    float2 v = make_float2(acc[mt][nt][0] + bx, acc[mt][nt][1] + by);
                    *(float2*)(Cout + (size_t)r0 * Ncols + col) = v;
                }
                if (r1 < M) {
                    float2 v = make_float2(acc[mt][nt][2] + bx, acc[mt][nt][3] + by);
                    *(float2*)(Cout + (size_t)r1 * Ncols + col) = v;
                }
            } else {
                size_t stride = (size_t)Ncols >> 1;
                if (r0 < M) {
                    float a = acc[mt][nt][0], b = acc[mt][nt][1];
                    Chi[r0 * stride + (col >> 1)] = pack_bf16(a, b);
                    Clo[r0 * stride + (col >> 1)] = pack_bf16(a - bf16_val(a), b - bf16_val(b));
                }
                if (r1 < M) {
                    float a = acc[mt][nt][2], b = acc[mt][nt][3];
                    Chi[r1 * stride + (col >> 1)] = pack_bf16(a, b);
                    Clo[r1 * stride + (col >> 1)] = pack_bf16(a - bf16_val(a), b - bf16_val(b));
                }
            }
        }
    }
}

// ===========================================================================
// Bias precompute, padded to [H][896][896], -1e30 outside valid range (mask)
// ===========================================================================
__global__ void bias_kernel(const float* __restrict__ rel_table,
                            const float* __restrict__ g2l,
                            const float* __restrict__ g2g) {
    size_t idx = (size_t)blockIdx.x * blockDim.x + threadIdx.x;
    size_t total = (size_t)H_ * NP_ * NP_;
    if (idx >= total) return;
    int h = (int)(idx / ((size_t)NP_ * NP_));
    size_t r = idx % ((size_t)NP_ * NP_);
    int i = (int)(r / NP_);
    int j = (int)(r % NP_);
    float v;
    if (i < N_ && j < N_) {
        if (i == 0) {
            v = (j == 0) ? g2g[h] : g2l[h];
        } else if (j == 0) {
            v = g2l[H_ + h];
        } else {
            int li = i - 1, lj = j - 1;
            int qx = li / W_, qy = li % W_;
            int kx = lj / W_, ky = lj % W_;
            int ridx = (qx - kx + W_ - 1) * NB_ + (qy - ky + W_ - 1);
            v = rel_table[ridx * H_ + h];
        }
    } else {
        v = -1e30f;
    }
    g_bias[idx] = v;
}

// ===========================================================================
// V transpose: g_qkvh/l V-section [token][d] -> g_vth/l [bh][d][token], bf16
// ===========================================================================
__global__ void transpose_v() {
    __shared__ uint32_t tile[64][33];
    int tid = threadIdx.x;
    int tc = blockIdx.x, bh = blockIdx.y;
    int b = bh / H_, h = bh % H_;
    int t0 = tc * 64;
#pragma unroll
    for (int phase = 0; phase < 2; ++phase) {
        const uint32_t* src = (const uint32_t*)(phase ? g_qkvl : g_qkvh);
        uint32_t* dst = (uint32_t*)(phase ? g_vtl : g_vth);
#pragma unroll
        for (int it = 0; it < 8; ++it) {
            int idx = it * 256 + tid;
            int t = idx >> 5, d2 = idx & 31;
            int tok = t0 + t;
            uint32_t v = 0;
            if (tok < N_) v = src[(size_t)(b * N_ + tok) * 1152 + 768 + h * 32 + d2];
            tile[t][d2] = v;
        }
        __syncthreads();
#pragma unroll
        for (int it = 0; it < 8; ++it) {
            int idx = it * 256 + tid;
            int d = idx >> 5, t2 = idx & 31;
            uint32_t w0 = tile[2 * t2][d >> 1];
            uint32_t w1 = tile[2 * t2 + 1][d >> 1];
            uint16_t x0 = (d & 1) ? (uint16_t)(w0 >> 16) : (uint16_t)(w0 & 0xffff);
            uint16_t x1 = (d & 1) ? (uint16_t)(w1 >> 16) : (uint16_t)(w1 & 0xffff);
            dst[((size_t)bh * 64 + d) * (NP_ / 2) + tc * 32 + t2] =
                (uint32_t)x0 | ((uint32_t)x1 << 16);
        }
        __syncthreads();
    }
}

// ===========================================================================
// Flash attention with mma.sync (bf16 hi/lo on both GEMMs)
// ===========================================================================
#define FQSM 16384
#define FSTAGE 65536
#define FLASH_SMEM (2 * FQSM + 2 * FSTAGE)   // 163840

__global__ __launch_bounds__(256)
void flash_mma() {
    extern __shared__ char smem[];
    uint32_t sb = smem_to_u32(smem);
    int tid = threadIdx.x, lane = tid & 31, w = tid >> 5;
    int qt = blockIdx.x, bh = blockIdx.y;
    int b = bh / H_, h = bh % H_;
    int wm = w * 16;
    int gid = lane >> 2, tig = lane & 3;

    uint32_t aRow = lane & 15,  aCol = (lane >> 4) * 16;
    uint32_t bRow = (lane & 7) + ((lane >> 4) & 1) * 8;
    uint32_t bCol = ((lane >> 3) & 1) * 16;

#pragma unroll
    for (int it = 0; it < 8; ++it) {
        int g = it * 256 + tid;
        int mat = g >> 10;
        int idx = g & 1023;
        int r = idx >> 3, c16 = idx & 7;
        const __nv_bfloat16* src =
            (mat ? g_qkvl : g_qkvh) +
            (size_t)(b * N_ + qt * 128 + r) * (3 * C_) + h * 64 + c16 * 8;
        uint32_t off = (uint32_t)(r * 128 + c16 * 16);
        cp_async16(sb + mat * FQSM + SMEM_SWIZZLE_128B(off), src);
    }
    CP_COMMIT();

    auto prefetchKV = [&](int c) {
        uint32_t kb = sb + 2 * FQSM + (uint32_t)(c & 1) * FSTAGE;
#pragma unroll
        for (int it = 0; it < 16; ++it) {
            int g = it * 256 + tid;
            int mat = g >> 10;
            int idx = g & 1023;
            if (mat < 2) {
                int r = idx >> 3, c16 = idx & 7;
                const __nv_bfloat16* src =
                    (mat ? g_qkvl : g_qkvh) +
                    (size_t)(b * N_ + c * 128 + r) * (3 * C_) + C_ + h * 64 + c16 * 8;
                uint32_t off = (uint32_t)(r * 128 + c16 * 16);
                cp_async16(kb + mat * 16384 + SMEM_SWIZZLE_128B(off), src);
            } else {
                int d = idx >> 4, g16 = idx & 15;
                int half = g16 >> 3, cc = g16 & 7;
                const __nv_bfloat16* src =
                    (mat == 2 ? g_vth : g_vtl) +
                    ((size_t)bh * 64 + d) * NP_ + c * 128 + half * 64 + cc * 8;
                uint32_t off = (uint32_t)(d * 128 + cc * 16);
                cp_async16(kb + mat * 16384 + half * 8192 + SMEM_SWIZZLE_128B(off), src);
            }
        }
        CP_COMMIT();
    };

    prefetchKV(0);
    CP_WAIT(0);
    __syncthreads();

    float m0 = -1e30f, m1 = -1e30f, l0 = 0.f, l1 = 0.f;
    float accO[8][4];
#pragma unroll
    for (int i = 0; i < 8; ++i)
#pragma unroll
        for (int j = 0; j < 4; ++j) accO[i][j] = 0.f;

    const int i0 = qt * 128 + wm + gid;
    const float* bp = g_bias + (size_t)h * NP_ * NP_ + (size_t)i0 * NP_;

    for (int c = 0; c < 7; ++c) {
        if (c + 1 < 7) prefetchKV(c + 1);
        uint32_t kb = sb + 2 * FQSM + (uint32_t)(c & 1) * FSTAGE;

        float sacc[16][4];
#pragma unroll
        for (int i = 0; i < 16; ++i)
#pragma unroll
            for (int j = 0; j < 4; ++j) sacc[i][j] = 0.f;

#pragma unroll
        for (int k16 = 0; k16 < 4; ++k16) {
            uint32_t aoff = SMEM_SWIZZLE_128B(
                (uint32_t)((wm + aRow) * 128 + k16 * 32 + aCol));
            uint32_t qh[4], ql[4];
            ldsm_x4(qh, sb + aoff);
            ldsm_x4(ql, sb + FQSM + aoff);
#pragma unroll
            for (int nt2 = 0; nt2 < 8; ++nt2) {
                uint32_t boff = SMEM_SWIZZLE_128B(
                    (uint32_t)((nt2 * 16 + bRow) * 128 + k16 * 32 + bCol));
                uint32_t kh[4], kl[4];
                ldsm_x4(kh, kb + boff);
                ldsm_x4(kl, kb + 16384 + boff);
                mma16816(sacc[2*nt2],   qh, kh[0], kh[1]);
                mma16816(sacc[2*nt2+1], qh, kh[2], kh[3]);
                mma16816(sacc[2*nt2],   qh, kl[0], kl[1]);
                mma16816(sacc[2*nt2+1], qh, kl[2], kl[3]);
                mma16816(sacc[2*nt2],   ql, kh[0], kh[1]);
                mma16816(sacc[2*nt2+1], ql, kh[2], kh[3]);
            }
        }

        float cm0 = -1e30f, cm1 = -1e30f;
#pragma unroll
        for (int nt = 0; nt < 16; ++nt) {
            int j = c * 128 + nt * 8 + tig * 2;
            float2 b0 = *(const float2*)(bp + j);
            float2 b1 = *(const float2*)(bp + 8 * NP_ + j);
            sacc[nt][0] = fmaf(sacc[nt][0], 0.125f, b0.x);
            sacc[nt][1] = fmaf(sacc[nt][1], 0.125f, b0.y);
            sacc[nt][2] = fmaf(sacc[nt][2], 0.125f, b1.x);
            sacc[nt][3] = fmaf(sacc[nt][3], 0.125f, b1.y);
            cm0 = fmaxf(cm0, fmaxf(sacc[nt][0], sacc[nt][1]));
            cm1 = fmaxf(cm1, fmaxf(sacc[nt][2], sacc[nt][3]));
        }
#pragma unroll
        for (int ofs = 1; ofs < 4; ofs <<= 1) {
            cm0 = fmaxf(cm0, __shfl_xor_sync(0xffffffffu, cm0, ofs));
            cm1 = fmaxf(cm1, __shfl_xor_sync(0xffffffffu, cm1, ofs));
        }

        float mn0 = fmaxf(m0, cm0), mn1 = fmaxf(m1, cm1);
        float al0 = __expf(m0 - mn0), al1 = __expf(m1 - mn1);
        float rs0 = 0.f, rs1 = 0.f;
#pragma unroll
        for (int nt = 0; nt < 16; ++nt) {
            float p0 = __expf(sacc[nt][0] - mn0);
            float p1 = __expf(sacc[nt][1] - mn0);
            float p2 = __expf(sacc[nt][2] - mn1);
            float p3 = __expf(sacc[nt][3] - mn1);
            sacc[nt][0] = p0; sacc[nt][1] = p1;
            sacc[nt][2] = p2; sacc[nt][3] = p3;
            rs0 += p0 + p1; rs1 += p2 + p3;
        }
#pragma unroll
        for (int ofs = 1; ofs < 4; ofs <<= 1) {
            rs0 += __shfl_xor_sync(0xffffffffu, rs0, ofs);
            rs1 += __shfl_xor_sync(0xffffffffu, rs1, ofs);
        }
        l0 = l0 * al0 + rs0; m0 = mn0;
        l1 = l1 * al1 + rs1; m1 = mn1;
#pragma unroll
        for (int i = 0; i < 8; ++i) {
            accO[i][0] *= al0; accO[i][1] *= al0;
            accO[i][2] *= al1; accO[i][3] *= al1;
        }

#pragma unroll
        for (int kv = 0; kv < 8; ++kv) {
            float p00 = sacc[2*kv][0],   p01 = sacc[2*kv][1];
            float p02 = sacc[2*kv][2],   p03 = sacc[2*kv][3];
            float p10 = sacc[2*kv+1][0], p11 = sacc[2*kv+1][1];
            float p12 = sacc[2*kv+1][2], p13 = sacc[2*kv+1][3];
            uint32_t ph[4], pl[4];
            ph[0] = pack_bf16(p00, p01);
            ph[1] = pack_bf16(p02, p03);
            ph[2] = pack_bf16(p10, p11);
            ph[3] = pack_bf16(p12, p13);
            pl[0] = pack_bf16(p00 - bf16_val(p00), p01 - bf16_val(p01));
            pl[1] = pack_bf16(p02 - bf16_val(p02), p03 - bf16_val(p03));
            pl[2] = pack_bf16(p10 - bf16_val(p10), p11 - bf16_val(p11));
            pl[3] = pack_bf16(p12 - bf16_val(p12), p13 - bf16_val(p13));

            int half = kv >> 2, kk = kv & 3;
            uint32_t vb = kb + 32768 + half * 8192;
#pragma unroll
            for (int nt2 = 0; nt2 < 4; ++nt2) {
                uint32_t boff = SMEM_SWIZZLE_128B(
                    (uint32_t)((nt2 * 16 + bRow) * 128 + kk * 32 + bCol));
                uint32_t vh[4], vl[4];
                ldsm_x4(vh, vb + boff);
                ldsm_x4(vl, vb + 16384 + boff);
                mma16816(accO[2*nt2],   ph, vh[0], vh[1]);
                mma16816(accO[2*nt2+1], ph, vh[2], vh[3]);
                mma16816(accO[2*nt2],   ph, vl[0], vl[1]);
                mma16816(accO[2*nt2+1], ph, vl[2], vl[3]);
                mma16816(accO[2*nt2],   pl, vh[0], vh[1]);
                mma16816(accO[2*nt2+1], pl, vh[2], vh[3]);
            }
        }

        if (c + 1 < 7) CP_WAIT(0);
        __syncthreads();
    }

    float rn0 = 1.f / l0, rn1 = 1.f / l1;
    uint32_t* oh = (uint32_t*)g_ah;
    uint32_t* ol = (uint32_t*)g_al;
#pragma unroll
    for (int nt = 0; nt < 8; ++nt) {
        int dc = h * 64 + nt * 8 + tig * 2;
        if (i0 < N_) {
            float a = accO[nt][0] * rn0, bb = accO[nt][1] * rn0;
            size_t o = (size_t)(b * N_ + i0) * 384 + (dc >> 1);
            oh[o] = pack_bf16(a, bb);
            ol[o] = pack_bf16(a - bf16_val(a), bb - bf16_val(bb));
        }
        if (i0 + 8 < N_) {
            float a = accO[nt][2] * rn1, bb = accO[nt][3] * rn1;
            size_t o = (size_t)(b * N_ + i0 + 8) * 384 + (dc >> 1);
            oh[o] = pack_bf16(a, bb);
            ol[o] = pack_bf16(a - bf16_val(a), bb - bf16_val(bb));
        }
    }
}

// ===========================================================================
// launch
// ===========================================================================
extern "C" void kernel_launch(void* const* d_in, const int* in_sizes, int n_in,
                              void* d_out, int out_size) {
    (void)in_sizes; (void)n_in; (void)out_size;
    const float* x         = (const float*)d_in[0];
    const float* qkv_w     = (const float*)d_in[1];
    const float* proj_w    = (const float*)d_in[2];
    const float* proj_b    = (const float*)d_in[3];
    const float* rel_table = (const float*)d_in[4];
    const float* g2l       = (const float*)d_in[5];
    const float* g2g       = (const float*)d_in[6];
    float* out = (float*)d_out;

    __nv_bfloat16 *xh, *xl, *ah, *al, *qwh, *qwl, *pwh, *pwl, *qkvh, *qkvl;
    cudaGetSymbolAddress((void**)&xh, g_xh);
    cudaGetSymbolAddress((void**)&xl, g_xl);
    cudaGetSymbolAddress((void**)&ah, g_ah);
    cudaGetSymbolAddress((void**)&al, g_al);
    cudaGetSymbolAddress((void**)&qwh, g_qwh);
    cudaGetSymbolAddress((void**)&qwl, g_qwl);
    cudaGetSymbolAddress((void**)&pwh, g_pwh);
    cudaGetSymbolAddress((void**)&pwl, g_pwl);
    cudaGetSymbolAddress((void**)&qkvh, g_qkvh);
    cudaGetSymbolAddress((void**)&qkvl, g_qkvl);

    cudaFuncSetAttribute(gemm_mma<0>,
                         cudaFuncAttributeMaxDynamicSharedMemorySize, GEMM_SMEM);
    cudaFuncSetAttribute(gemm_mma<1>,
                         cudaFuncAttributeMaxDynamicSharedMemorySize, GEMM_SMEM);
    cudaFuncSetAttribute(flash_mma,
                         cudaFuncAttributeMaxDynamicSharedMemorySize, FLASH_SMEM);

    // splits
    {
        int tot = MPAD * (K_ / 4);
        split_kernel<<<(tot + 255) / 256, 256>>>(x, xh, xl, M_, MPAD);
    }
    {
        int tot = 3 * C_ * (K_ / 4);
        split_kernel<<<(tot + 255) / 256, 256>>>(qkv_w, qwh, qwl, 3 * C_, 3 * C_);
    }
    {
        int tot = C_ * (K_ / 4);
        split_kernel<<<(tot + 255) / 256, 256>>>(proj_w, pwh, pwl, C_, C_);
    }

    // padded bias table
    {
        size_t total = (size_t)H_ * NP_ * NP_;
        bias_kernel<<<(unsigned)((total + 255) / 256), 256>>>(rel_table, g2l, g2g);
    }

    // 1) QKV GEMM -> bf16 hi/lo
    gemm_mma<1><<<dim3(3 * C_ / 128, MPAD / 128), 256, GEMM_SMEM>>>(
        xh, xl, qwh, qwl, nullptr, nullptr,
        (uint32_t*)qkvh, (uint32_t*)qkvl, M_, 3 * C_);

    // 2) V transpose
    transpose_v<<<dim3(NP_ / 64, BH_), 256>>>();

    // 3) flash attention (tensor cores) -> g_ah/g_al
    flash_mma<<<dim3(NP_ / 128, BH_), 256, FLASH_SMEM>>>();

    // 4) proj GEMM + bias -> out
    gemm_mma<0><<<dim3(C_ / 128, MPAD / 128), 256, GEMM_SMEM>>>(
        ah, al, pwh, pwl, proj_b, out, nullptr, nullptr, M_, C_);
}